// round 15
// baseline (speedup 1.0000x reference)
#include <cuda_runtime.h>
#include <cuda_bf16.h>
#include <math.h>
#include <stdint.h>

// Problem constants
#define BB   4
#define TT   4096
#define DD   1024
#define HH   16
#define HDIM 64
#define KK   32
#define D3   (3*DD)
#define BH   (BB*HH)

#define TSPLIT 16   // T split for xs partials
#define KSPL_B 4    // K split for spec3 GEMM (256 k each)
#define KSPL_D 8    // K split for M GEMM (128 k each)

typedef unsigned long long ull;

// ---- packed f32x2 helpers (FFMA2) ----
__device__ __forceinline__ ull pk2(float lo, float hi) {
    ull r; asm("mov.b64 %0, {%1,%2};" : "=l"(r) : "f"(lo), "f"(hi)); return r;
}
__device__ __forceinline__ void ffma2(ull& d, ull a, ull b) {
    asm("fma.rn.f32x2 %0, %1, %2, %3;" : "=l"(d) : "l"(a), "l"(b), "l"(d));
}

// ---- tf32 helpers (out_kernel) ----
__device__ __forceinline__ float tf32_rna(float f) {
    unsigned u; asm("cvt.rna.tf32.f32 %0, %1;" : "=r"(u) : "f"(f));
    return __uint_as_float(u);
}
__device__ __forceinline__ void mma_tf32(float* c, const float* a, float b0, float b1) {
    asm volatile(
        "mma.sync.aligned.m16n8k8.row.col.f32.tf32.tf32.f32 "
        "{%0,%1,%2,%3},{%4,%5,%6,%7},{%8,%9},{%0,%1,%2,%3};"
        : "+f"(c[0]), "+f"(c[1]), "+f"(c[2]), "+f"(c[3])
        : "r"(__float_as_uint(a[0])), "r"(__float_as_uint(a[1])),
          "r"(__float_as_uint(a[2])), "r"(__float_as_uint(a[3])),
          "r"(__float_as_uint(b0)),  "r"(__float_as_uint(b1)));
}

// ---- bf16 helpers ----
__device__ __forceinline__ unsigned pkbf(float hi, float lo) {
    unsigned r; asm("cvt.rn.bf16x2.f32 %0, %1, %2;" : "=r"(r) : "f"(hi), "f"(lo));
    return r;
}
__device__ __forceinline__ void split2(float v0, float v1, unsigned& h, unsigned& l) {
    h = pkbf(v1, v0);
    float h0 = __uint_as_float(h << 16);
    float h1 = __uint_as_float(h & 0xffff0000u);
    l = pkbf(v1 - h1, v0 - h0);
}
__device__ __forceinline__ void mma_bf16(float* c, const unsigned* a, unsigned b0, unsigned b1) {
    asm volatile(
        "mma.sync.aligned.m16n8k16.row.col.f32.bf16.bf16.f32 "
        "{%0,%1,%2,%3},{%4,%5,%6,%7},{%8,%9},{%0,%1,%2,%3};"
        : "+f"(c[0]), "+f"(c[1]), "+f"(c[2]), "+f"(c[3])
        : "r"(a[0]), "r"(a[1]), "r"(a[2]), "r"(a[3]), "r"(b0), "r"(b1));
}

// ---------------- scratch (device globals; no allocation) ----------------
__device__ float g_xs_part[TSPLIT*BB*KK*DD];
__device__ float g_xm_part[TSPLIT*BB*DD];
__device__ float g_xs[BB*KK*DD];                 // (b*32+k, j) fp32
__device__ unsigned g_xs_h[BB*KK*DD/2];          // pre-split bf16 hi pairs
__device__ unsigned g_xs_l[BB*KK*DD/2];          // pre-split bf16 lo pairs
__device__ float g_xm[BB*DD];
__device__ float g_qm[BB*DD];                    // qm[b, h*64+d]
__device__ float g_sp_part[KSPL_B*BB*KK*D3];     // spec3 partials (4 slabs)
__device__ float g_resp[BH*KK];
__device__ float g_M_part[KSPL_D*BB*KK*DD];
__device__ float g_M[BB*KK*DD];                  // (b, k, i)

// =============== 1) xs[b,k,j] = sum_t basis[b,t,k]*x[b,t,j] (+xm) ============
// bf16 3-term tensor version. grid (b=4, jt=4, ts=16), 256 threads.
__global__ void __launch_bounds__(256)
xs_kernel(const float* __restrict__ x, const float* __restrict__ basis) {
    __shared__ float xt[32][260];
    __shared__ unsigned bph[32][20];
    __shared__ unsigned bpl[32][20];
    __shared__ float xmred[4][256];
    const int b  = blockIdx.x;
    const int jt = blockIdx.y;
    const int ts = blockIdx.z;
    const int tid  = threadIdx.x;
    const int w    = tid >> 5;
    const int lane = tid & 31;
    const int g    = lane >> 2;
    const int tg   = lane & 3;
    const int j0   = jt * 256;

    float c[2][4][4];
#pragma unroll
    for (int i = 0; i < 2; i++)
#pragma unroll
        for (int j = 0; j < 4; j++)
#pragma unroll
            for (int r = 0; r < 4; r++) c[i][j][r] = 0.f;
    float4 xmacc = make_float4(0.f, 0.f, 0.f, 0.f);

    float4 xv[8];
    float4 bv0, bv1;
    const int bt2 = tid >> 3;
    const int bk4 = (tid & 7) * 4;

    {
        const int t0 = ts*256;
#pragma unroll
        for (int i = 0; i < 8; i++) {
            int f = tid + 256*i;
            int row = f >> 6, c4 = (f & 63) * 4;
            xv[i] = *(const float4*)(x + ((size_t)(b*TT + t0 + row))*DD + j0 + c4);
        }
        if (tid < 128) {
            bv0 = *(const float4*)(basis + ((size_t)(b*TT + t0 + 2*bt2  ))*KK + bk4);
            bv1 = *(const float4*)(basis + ((size_t)(b*TT + t0 + 2*bt2+1))*KK + bk4);
        }
    }

    for (int tc = 0; tc < 8; tc++) {
#pragma unroll
        for (int i = 0; i < 8; i++) {
            int f = tid + 256*i;
            int row = f >> 6, c4 = (f & 63) * 4;
            *(float4*)&xt[row][c4] = xv[i];
            xmacc.x += xv[i].x; xmacc.y += xv[i].y; xmacc.z += xv[i].z; xmacc.w += xv[i].w;
        }
        if (tid < 128) {
            float e0[4] = {bv0.x, bv0.y, bv0.z, bv0.w};
            float e1[4] = {bv1.x, bv1.y, bv1.z, bv1.w};
#pragma unroll
            for (int kk = 0; kk < 4; kk++) {
                unsigned h, l;
                split2(e0[kk], e1[kk], h, l);
                bph[bk4 + kk][bt2] = h;
                bpl[bk4 + kk][bt2] = l;
            }
        }
        __syncthreads();

        if (tc < 7) {
            const int t0 = ts*256 + (tc+1)*32;
#pragma unroll
            for (int i = 0; i < 8; i++) {
                int f = tid + 256*i;
                int row = f >> 6, c4 = (f & 63) * 4;
                xv[i] = *(const float4*)(x + ((size_t)(b*TT + t0 + row))*DD + j0 + c4);
            }
            if (tid < 128) {
                bv0 = *(const float4*)(basis + ((size_t)(b*TT + t0 + 2*bt2  ))*KK + bk4);
                bv1 = *(const float4*)(basis + ((size_t)(b*TT + t0 + 2*bt2+1))*KK + bk4);
            }
        }

#pragma unroll
        for (int s = 0; s < 2; s++) {
            unsigned ah[2][4], al[2][4];
#pragma unroll
            for (int mt = 0; mt < 2; mt++) {
                int mb = mt*16;
                ah[mt][0] = bph[mb+g  ][s*8+tg];   ah[mt][1] = bph[mb+g+8][s*8+tg];
                ah[mt][2] = bph[mb+g  ][s*8+tg+4]; ah[mt][3] = bph[mb+g+8][s*8+tg+4];
                al[mt][0] = bpl[mb+g  ][s*8+tg];   al[mt][1] = bpl[mb+g+8][s*8+tg];
                al[mt][2] = bpl[mb+g  ][s*8+tg+4]; al[mt][3] = bpl[mb+g+8][s*8+tg+4];
            }
#pragma unroll
            for (int nt = 0; nt < 4; nt++) {
                int jl = w*32 + nt*8 + g;
                int tb = s*16 + 2*tg;
                float x0 = xt[tb  ][jl], x1 = xt[tb+1][jl];
                float x2 = xt[tb+8][jl], x3 = xt[tb+9][jl];
                unsigned b0h, b0l, b1h, b1l;
                split2(x0, x1, b0h, b0l);
                split2(x2, x3, b1h, b1l);
#pragma unroll
                for (int mt = 0; mt < 2; mt++) {
                    mma_bf16(c[mt][nt], ah[mt], b0h, b1h);
                    mma_bf16(c[mt][nt], ah[mt], b0l, b1l);
                    mma_bf16(c[mt][nt], al[mt], b0h, b1h);
                }
            }
        }
        __syncthreads();
    }

#pragma unroll
    for (int mt = 0; mt < 2; mt++)
#pragma unroll
        for (int nt = 0; nt < 4; nt++) {
            int krow = mt*16 + g;
            int jc = j0 + w*32 + nt*8 + 2*tg;
            size_t base = (((size_t)ts*BB + b)*KK + krow)*DD + jc;
            *(float2*)&g_xs_part[base]        = make_float2(c[mt][nt][0], c[mt][nt][1]);
            *(float2*)&g_xs_part[base + 8*DD] = make_float2(c[mt][nt][2], c[mt][nt][3]);
        }
    *(float4*)&xmred[tid >> 6][(tid & 63) * 4] = xmacc;
    __syncthreads();
    if (tid < 64) {
        float4 s = make_float4(0.f, 0.f, 0.f, 0.f);
#pragma unroll
        for (int r = 0; r < 4; r++) {
            float4 v = *(const float4*)&xmred[r][tid*4];
            s.x += v.x; s.y += v.y; s.z += v.z; s.w += v.w;
        }
        *(float4*)&g_xm_part[((size_t)ts*BB + b)*DD + j0 + tid*4] = s;
    }
}

// =============== 2) reduce xs partials + xm, emit pre-split bf16 pairs ======
// grid 256, 256 threads; one float2 (= one k-pair) per thread.
__global__ void reduceA_kernel() {
    int gid = blockIdx.x * 256 + threadIdx.x;   // 65536 float2 items
    float2 s = make_float2(0.f, 0.f);
#pragma unroll
    for (int ts = 0; ts < TSPLIT; ts++) {
        float2 v = ((const float2*)g_xs_part)[(size_t)ts*65536 + gid];
        s.x += v.x; s.y += v.y;
    }
    ((float2*)g_xs)[gid] = s;
    unsigned h, l;
    split2(s.x, s.y, h, l);
    g_xs_h[gid] = h;
    g_xs_l[gid] = l;
    if (gid < BB*DD) {
        float m = 0.f;
#pragma unroll
        for (int ts = 0; ts < TSPLIT; ts++) m += g_xm_part[(size_t)ts*BB*DD + gid];
        g_xm[gid] = m * (1.0f / (float)TT);
    }
}

// =============== 3) spec3 partials = xs(128x1024) @ Wqkv^T, bf16 3-term ======
// grid (nt=96, ks=4), 256 threads; block M=128, N=32, K=256 in chunks of 64.
// A comes pre-split from g_xs_h/g_xs_l (pure copy staging).
__global__ void __launch_bounds__(256)
gemmB_kernel(const float* __restrict__ Wqkv) {
    __shared__ unsigned Aph[128][36];    // [m][kpair 0..31], pad 36
    __shared__ unsigned Apl[128][36];
    __shared__ unsigned Bph[32][36];
    __shared__ unsigned Bpl[32][36];
    const int bn = blockIdx.x * 32;
    const int ks = blockIdx.y;
    const int tid  = threadIdx.x;
    const int w    = tid >> 5;
    const int lane = tid & 31;
    const int g    = lane >> 2;
    const int tg   = lane & 3;
    const int wm   = w >> 1;
    const int wn   = w & 1;

    float c[2][2][4];
#pragma unroll
    for (int i = 0; i < 2; i++)
#pragma unroll
        for (int j = 0; j < 2; j++)
#pragma unroll
            for (int r = 0; r < 4; r++) c[i][j][r] = 0.f;

    for (int kc = 0; kc < 4; kc++) {
        const int k0 = ks*256 + kc*64;
        const int pb = k0 >> 1;              // pair base (32 pairs per chunk)
        // stage A from pre-split arrays: 128 rows x 32 pairs, hi+lo
#pragma unroll
        for (int i = 0; i < 4; i++) {
            int f = tid + 256*i;             // 0..1023 uint4 slots
            int m = f >> 3, pg = (f & 7) * 4;
            uint4 vh = *(const uint4*)&g_xs_h[(size_t)m*512 + pb + pg];
            uint4 vl = *(const uint4*)&g_xs_l[(size_t)m*512 + pb + pg];
            Aph[m][pg+0] = vh.x; Aph[m][pg+1] = vh.y; Aph[m][pg+2] = vh.z; Aph[m][pg+3] = vh.w;
            Apl[m][pg+0] = vl.x; Apl[m][pg+1] = vl.y; Apl[m][pg+2] = vl.z; Apl[m][pg+3] = vl.w;
        }
        // stage B (Wqkv 32n x 64k): split on the fly (not redundant across blocks)
#pragma unroll
        for (int i = 0; i < 2; i++) {
            int f = tid + 256*i;
            int n = f >> 4, kg = f & 15;
            float4 v = *(const float4*)(Wqkv + (size_t)(bn + n)*DD + k0 + kg*4);
            unsigned h0, l0, h1, l1;
            split2(v.x, v.y, h0, l0);
            split2(v.z, v.w, h1, l1);
            Bph[n][kg*2] = h0; Bph[n][kg*2+1] = h1;
            Bpl[n][kg*2] = l0; Bpl[n][kg*2+1] = l1;
        }
        __syncthreads();
#pragma unroll
        for (int s = 0; s < 4; s++) {
            unsigned ah[2][4], al[2][4];
#pragma unroll
            for (int mt = 0; mt < 2; mt++) {
                int mb = wm*32 + mt*16;
                ah[mt][0] = Aph[mb+g  ][s*8+tg];   ah[mt][1] = Aph[mb+g+8][s*8+tg];
                ah[mt][2] = Aph[mb+g  ][s*8+tg+4]; ah[mt][3] = Aph[mb+g+8][s*8+tg+4];
                al[mt][0] = Apl[mb+g  ][s*8+tg];   al[mt][1] = Apl[mb+g+8][s*8+tg];
                al[mt][2] = Apl[mb+g  ][s*8+tg+4]; al[mt][3] = Apl[mb+g+8][s*8+tg+4];
            }
#pragma unroll
            for (int nt = 0; nt < 2; nt++) {
                int nr = wn*16 + nt*8 + g;
                unsigned b0h = Bph[nr][s*8+tg], b1h = Bph[nr][s*8+tg+4];
                unsigned b0l = Bpl[nr][s*8+tg], b1l = Bpl[nr][s*8+tg+4];
#pragma unroll
                for (int mt = 0; mt < 2; mt++) {
                    mma_bf16(c[mt][nt], ah[mt], b0h, b1h);
                    mma_bf16(c[mt][nt], ah[mt], b0l, b1l);
                    mma_bf16(c[mt][nt], al[mt], b0h, b1h);
                }
            }
        }
        __syncthreads();
    }
#pragma unroll
    for (int mt = 0; mt < 2; mt++)
#pragma unroll
        for (int nt = 0; nt < 2; nt++) {
            int m = wm*32 + mt*16 + g;
            int n = bn + wn*16 + nt*8 + 2*tg;
            size_t base = ((size_t)ks*128 + m)*D3 + n;
            *(float2*)&g_sp_part[base]                = make_float2(c[mt][nt][0], c[mt][nt][1]);
            *(float2*)&g_sp_part[base + 8*(size_t)D3] = make_float2(c[mt][nt][2], c[mt][nt][3]);
        }
}

// =============== 4a) qm GEMV: qm[b,row] = dot(Wq[row], xm[b]) ===============
__global__ void __launch_bounds__(256)
qm_kernel(const float* __restrict__ Wqkv) {
    __shared__ float sxm[BB*DD];
    const int tid  = threadIdx.x;
    const int w    = tid >> 5;
    const int lane = tid & 31;
#pragma unroll
    for (int i = 0; i < 4; i++)
        ((float4*)sxm)[tid + 256*i] = ((const float4*)g_xm)[tid + 256*i];
    __syncthreads();

    const int row = blockIdx.x * 8 + w;
    const float4* wr = (const float4*)(Wqkv + (size_t)row*DD);
    float s0 = 0.f, s1 = 0.f, s2 = 0.f, s3 = 0.f;
#pragma unroll
    for (int i = 0; i < 8; i++) {
        float4 wv = wr[lane + 32*i];
        float4 x0 = *(const float4*)&sxm[0*DD + (lane + 32*i)*4];
        float4 x1 = *(const float4*)&sxm[1*DD + (lane + 32*i)*4];
        float4 x2 = *(const float4*)&sxm[2*DD + (lane + 32*i)*4];
        float4 x3 = *(const float4*)&sxm[3*DD + (lane + 32*i)*4];
        s0 += wv.x*x0.x + wv.y*x0.y + wv.z*x0.z + wv.w*x0.w;
        s1 += wv.x*x1.x + wv.y*x1.y + wv.z*x1.z + wv.w*x1.w;
        s2 += wv.x*x2.x + wv.y*x2.y + wv.z*x2.z + wv.w*x2.w;
        s3 += wv.x*x3.x + wv.y*x3.y + wv.z*x3.z + wv.w*x3.w;
    }
#pragma unroll
    for (int off = 16; off > 0; off >>= 1) {
        s0 += __shfl_down_sync(0xffffffffu, s0, off);
        s1 += __shfl_down_sync(0xffffffffu, s1, off);
        s2 += __shfl_down_sync(0xffffffffu, s2, off);
        s3 += __shfl_down_sync(0xffffffffu, s3, off);
    }
    if (lane == 0) {
        g_qm[0*DD + row] = s0;
        g_qm[1*DD + row] = s1;
        g_qm[2*DD + row] = s2;
        g_qm[3*DD + row] = s3;
    }
}

// =============== 4b) fused soliton ODE + pulse MLP ===============
__global__ void ps_kernel(const float* __restrict__ W1, const float* __restrict__ b1,
                          const float* __restrict__ W2, const float* __restrict__ b2,
                          const float* __restrict__ sfilt,
                          const float* __restrict__ pa, const float* __restrict__ pb,
                          float* __restrict__ out_pw, float* __restrict__ out_resp) {
    if (blockIdx.x < 64) {
        // ---- soliton ----
        const int bh = blockIdx.x;
        const int b = bh >> 4, h = bh & 15;
        const int k = threadIdx.x;
        if (k >= 32) return;
        const size_t m = (size_t)(b*KK + k);
        float dot = 0.f;
#pragma unroll
        for (int d = 0; d < HDIM/4; d++) {
            float4 qs = make_float4(0.f,0.f,0.f,0.f), ks4 = make_float4(0.f,0.f,0.f,0.f);
#pragma unroll
            for (int sl = 0; sl < KSPL_B; sl++) {
                const float* P = g_sp_part + ((size_t)sl*128 + m)*D3;
                float4 q = *(const float4*)(P + h*HDIM + d*4);
                float4 kv = *(const float4*)(P + DD + h*HDIM + d*4);
                qs.x += q.x; qs.y += q.y; qs.z += q.z; qs.w += q.w;
                ks4.x += kv.x; ks4.y += kv.y; ks4.z += kv.z; ks4.w += kv.w;
            }
            dot += qs.x*ks4.x + qs.y*ks4.y + qs.z*ks4.z + qs.w*ks4.w;
        }
        float filt = 1.f / (1.f + expf(-sfilt[h*KK + k]));
        float s = dot * 0.125f * filt;

        float scale = fmaxf(fabsf(s), 1e-6f);
        float sn = s / scale;
        float I  = (fabsf(s) > 0.5f) ? sn : 0.1f*sn;
        const float a = *pa, bcoef = *pb;
        const float dt = 0.2f;
        float v = 0.f, w = 0.f;
#pragma unroll
        for (int it = 0; it < 5; it++) {
            float dv = v - v*v*v*(1.f/3.f) - w + I;
            float dw = (v + a - bcoef*w) * 10.f;
            v = fminf(fmaxf(v + dt*dv, -3.f), 3.f);
            w = fminf(fmaxf(w + dt*dw, -3.f), 3.f);
        }
        float r = v * scale;
        g_resp[bh*KK + k]   = r;
        out_resp[bh*KK + k] = r;
    } else {
        // ---- pulse MLP ----
        __shared__ float qm[HDIM];
        __shared__ float h1[32];
        const int bh = blockIdx.x - 64;
        const int b = bh >> 4, h = bh & 15;
        const int d = threadIdx.x;
        qm[d] = g_qm[(size_t)b*DD + h*HDIM + d];
        __syncthreads();
        if (d < 32) {
            float a = b1[d];
#pragma unroll
            for (int j = 0; j < HDIM; j++) a += qm[j] * W1[d*HDIM + j];
            h1[d] = a / (1.f + expf(-a));
        }
        __syncthreads();
        if (d == 0) {
            float a = b2[0];
#pragma unroll
            for (int j = 0; j < 32; j++) a += h1[j] * W2[j];
            float spl = (a > 20.f) ? a : log1pf(expf(a));
            out_pw[bh] = 4.0f + spl;
        }
    }
}

// =============== 5) M[b] = (resp*v_spec)(32x1024) @ Wout^T, split-K ==========
__global__ void __launch_bounds__(256)
gemmD_kernel(const float* __restrict__ Wout) {
    __shared__ float As[8][32];
    __shared__ float Bs[8][128];
    const int bn = blockIdx.x * 128;
    const int ks = blockIdx.y;
    const int b  = blockIdx.z;
    const int tid = threadIdx.x;
    const int tx = tid & 31;
    const int my = tid >> 5;
    const int lr = tid >> 1, lc = (tid & 1) << 2;

    const float* Bp = Wout + (size_t)(bn + lr)*DD + ks*128 + lc;

    ull acc2[4][2];
#pragma unroll
    for (int i = 0; i < 4; i++) { acc2[i][0] = 0ull; acc2[i][1] = 0ull; }

    for (int k0 = 0; k0 < 128; k0 += 8) {
        if (tid < 64) {
            int ar = tid >> 1, ac = (tid & 1) << 2;
            int col = ks*128 + k0 + ac;
            size_t m = (size_t)(b*KK + ar);
            float4 av = make_float4(0.f,0.f,0.f,0.f);
#pragma unroll
            for (int sl = 0; sl < KSPL_B; sl++) {
                float4 a0 = *(const float4*)(g_sp_part + ((size_t)sl*128 + m)*D3 + 2*DD + col);
                av.x += a0.x; av.y += a0.y; av.z += a0.z; av.w += a0.w;
            }
            float r = g_resp[(b*HH + (col >> 6))*KK + ar];
            As[ac+0][ar] = av.x * r; As[ac+1][ar] = av.y * r;
            As[ac+2][ar] = av.z * r; As[ac+3][ar] = av.w * r;
        }
        float4 bv = *(const float4*)(Bp + k0);
        Bs[lc+0][lr] = bv.x; Bs[lc+1][lr] = bv.y; Bs[lc+2][lr] = bv.z; Bs[lc+3][lr] = bv.w;
        __syncthreads();
#pragma unroll
        for (int kk = 0; kk < 8; kk++) {
            ulonglong2 rb = *(const ulonglong2*)&Bs[kk][tx*4];
            float a0 = As[kk][my], a1 = As[kk][my+8], a2 = As[kk][my+16], a3 = As[kk][my+24];
            ull p0 = pk2(a0,a0), p1 = pk2(a1,a1), p2 = pk2(a2,a2), p3 = pk2(a3,a3);
            ffma2(acc2[0][0], p0, rb.x); ffma2(acc2[0][1], p0, rb.y);
            ffma2(acc2[1][0], p1, rb.x); ffma2(acc2[1][1], p1, rb.y);
            ffma2(acc2[2][0], p2, rb.x); ffma2(acc2[2][1], p2, rb.y);
            ffma2(acc2[3][0], p3, rb.x); ffma2(acc2[3][1], p3, rb.y);
        }
        __syncthreads();
    }
#pragma unroll
    for (int mi = 0; mi < 4; mi++) {
        int m = my + 8*mi;
        *(ulonglong2*)&g_M_part[(((size_t)ks*BB + b)*KK + m)*DD + bn + tx*4] =
            make_ulonglong2(acc2[mi][0], acc2[mi][1]);
    }
}

__global__ void reduceD_kernel() {
    int gid = blockIdx.x * 256 + threadIdx.x;   // 131072
    float s = 0.f;
#pragma unroll
    for (int ks = 0; ks < KSPL_D; ks++) s += g_M_part[(size_t)ks*131072 + gid];
    g_M[gid] = s;
}

// =============== 6) out[b,t,j] = sum_k basis[b,t,k] * M[b,k,j], tf32 tensor ==
__global__ void __launch_bounds__(256)
out_kernel(const float* __restrict__ basis, float* __restrict__ out) {
    __shared__ float Bh[64][36];
    __shared__ float Bl[64][36];
    __shared__ float Mh[32][72];
    __shared__ float Ml[32][72];
    const int tt = blockIdx.x, jt = blockIdx.y, b = blockIdx.z;
    const int t0 = tt*64, j0 = jt*64;
    const int tid  = threadIdx.x;
    const int w    = tid >> 5;
    const int lane = tid & 31;
    const int g    = lane >> 2;
    const int tg   = lane & 3;
    const int wm   = w >> 2;
    const int wn   = w & 3;

#pragma unroll
    for (int i = 0; i < 2; i++) {
        int f = tid + 256*i;
        int row = f >> 3, c4 = (f & 7) * 4;
        float4 v = *(const float4*)(basis + ((size_t)(b*TT + t0 + row))*KK + c4);
        float hx = tf32_rna(v.x), hy = tf32_rna(v.y), hz = tf32_rna(v.z), hw = tf32_rna(v.w);
        Bh[row][c4+0] = hx; Bh[row][c4+1] = hy; Bh[row][c4+2] = hz; Bh[row][c4+3] = hw;
        Bl[row][c4+0] = v.x - hx; Bl[row][c4+1] = v.y - hy;
        Bl[row][c4+2] = v.z - hz; Bl[row][c4+3] = v.w - hw;
    }
#pragma unroll
    for (int i = 0; i < 2; i++) {
        int f = tid + 256*i;
        int row = f >> 4, c4 = (f & 15) * 4;
        float4 v = *(const float4*)(g_M + ((size_t)b*KK + row)*DD + j0 + c4);
        float hx = tf32_rna(v.x), hy = tf32_rna(v.y), hz = tf32_rna(v.z), hw = tf32_rna(v.w);
        Mh[row][c4+0] = hx; Mh[row][c4+1] = hy; Mh[row][c4+2] = hz; Mh[row][c4+3] = hw;
        Ml[row][c4+0] = v.x - hx; Ml[row][c4+1] = v.y - hy;
        Ml[row][c4+2] = v.z - hz; Ml[row][c4+3] = v.w - hw;
    }
    __syncthreads();

    float c[2][2][4];
#pragma unroll
    for (int i = 0; i < 2; i++)
#pragma unroll
        for (int j = 0; j < 2; j++)
#pragma unroll
            for (int r = 0; r < 4; r++) c[i][j][r] = 0.f;

#pragma unroll
    for (int s = 0; s < 4; s++) {
        const int k0 = s*8 + tg, k1 = s*8 + tg + 4;
        float ah[2][4], al[2][4];
#pragma unroll
        for (int mt = 0; mt < 2; mt++) {
            int mb = wm*32 + mt*16;
            ah[mt][0] = Bh[mb+g][k0];  ah[mt][1] = Bh[mb+g+8][k0];
            ah[mt][2] = Bh[mb+g][k1];  ah[mt][3] = Bh[mb+g+8][k1];
            al[mt][0] = Bl[mb+g][k0];  al[mt][1] = Bl[mb+g+8][k0];
            al[mt][2] = Bl[mb+g][k1];  al[mt][3] = Bl[mb+g+8][k1];
        }
#pragma unroll
        for (int nt = 0; nt < 2; nt++) {
            int nc = wn*16 + nt*8 + g;
            float b0h = Mh[k0][nc], b1h = Mh[k1][nc];
            float b0l = Ml[k0][nc], b1l = Ml[k1][nc];
#pragma unroll
            for (int mt = 0; mt < 2; mt++) {
                mma_tf32(c[mt][nt], ah[mt], b0h, b1h);
                mma_tf32(c[mt][nt], ah[mt], b0l, b1l);
                mma_tf32(c[mt][nt], al[mt], b0h, b1h);
            }
        }
    }
#pragma unroll
    for (int mt = 0; mt < 2; mt++)
#pragma unroll
        for (int nt = 0; nt < 2; nt++) {
            int t = t0 + wm*32 + mt*16 + g;
            int jc = j0 + wn*16 + nt*8 + 2*tg;
            size_t base = ((size_t)b*TT + t)*DD + jc;
            *(float2*)(out + base)                = make_float2(c[mt][nt][0], c[mt][nt][1]);
            *(float2*)(out + base + 8*(size_t)DD) = make_float2(c[mt][nt][2], c[mt][nt][3]);
        }
}

// ---------------- launch ----------------
extern "C" void kernel_launch(void* const* d_in, const int* in_sizes, int n_in,
                              void* d_out, int out_size) {
    const float* x     = (const float*)d_in[0];
    const float* basis = (const float*)d_in[1];
    const float* Wqkv  = (const float*)d_in[2];
    const float* Wout  = (const float*)d_in[3];
    const float* pa    = (const float*)d_in[4];
    const float* pb    = (const float*)d_in[5];
    const float* W1    = (const float*)d_in[6];
    const float* b1    = (const float*)d_in[7];
    const float* W2    = (const float*)d_in[8];
    const float* b2    = (const float*)d_in[9];
    const float* sfilt = (const float*)d_in[10];

    float* out      = (float*)d_out;                 // (B,T,D)
    float* out_pw   = out + (size_t)BB*TT*DD;        // (B,H)
    float* out_resp = out_pw + BH;                   // (B,H,K)

    xs_kernel<<<dim3(BB, 4, TSPLIT), 256>>>(x, basis);
    reduceA_kernel<<<256, 256>>>();
    qm_kernel<<<128, 256>>>(Wqkv);
    gemmB_kernel<<<dim3(96, KSPL_B), 256>>>(Wqkv);
    ps_kernel<<<128, 64>>>(W1, b1, W2, b2, sfilt, pa, pb, out_pw, out_resp);
    gemmD_kernel<<<dim3(8, KSPL_D, BB), 256>>>(Wout);
    reduceD_kernel<<<512, 256>>>();
    out_kernel<<<dim3(64, 16, BB), 256>>>(basis, out);
}

// round 16
// speedup vs baseline: 1.0315x; 1.0315x over previous
#include <cuda_runtime.h>
#include <cuda_bf16.h>
#include <math.h>
#include <stdint.h>

// Problem constants
#define BB   4
#define TT   4096
#define DD   1024
#define HH   16
#define HDIM 64
#define KK   32
#define D3   (3*DD)
#define BH   (BB*HH)

#define TSPLIT 16   // T split for xs partials
#define KSPL_B 2    // K split for spec3 GEMM (512 k each)
#define KSPL_D 8    // K split for M GEMM (128 k each)

typedef unsigned long long ull;

// ---- packed f32x2 helpers (FFMA2) ----
__device__ __forceinline__ ull pk2(float lo, float hi) {
    ull r; asm("mov.b64 %0, {%1,%2};" : "=l"(r) : "f"(lo), "f"(hi)); return r;
}
__device__ __forceinline__ void ffma2(ull& d, ull a, ull b) {
    asm("fma.rn.f32x2 %0, %1, %2, %3;" : "=l"(d) : "l"(a), "l"(b), "l"(d));
}

// ---- tf32 helpers (out_kernel) ----
__device__ __forceinline__ float tf32_rna(float f) {
    unsigned u; asm("cvt.rna.tf32.f32 %0, %1;" : "=r"(u) : "f"(f));
    return __uint_as_float(u);
}
__device__ __forceinline__ void mma_tf32(float* c, const float* a, float b0, float b1) {
    asm volatile(
        "mma.sync.aligned.m16n8k8.row.col.f32.tf32.tf32.f32 "
        "{%0,%1,%2,%3},{%4,%5,%6,%7},{%8,%9},{%0,%1,%2,%3};"
        : "+f"(c[0]), "+f"(c[1]), "+f"(c[2]), "+f"(c[3])
        : "r"(__float_as_uint(a[0])), "r"(__float_as_uint(a[1])),
          "r"(__float_as_uint(a[2])), "r"(__float_as_uint(a[3])),
          "r"(__float_as_uint(b0)),  "r"(__float_as_uint(b1)));
}

// ---- bf16 helpers ----
__device__ __forceinline__ unsigned pkbf(float hi, float lo) {
    unsigned r; asm("cvt.rn.bf16x2.f32 %0, %1, %2;" : "=r"(r) : "f"(hi), "f"(lo));
    return r;
}
__device__ __forceinline__ void split2(float v0, float v1, unsigned& h, unsigned& l) {
    h = pkbf(v1, v0);
    float h0 = __uint_as_float(h << 16);
    float h1 = __uint_as_float(h & 0xffff0000u);
    l = pkbf(v1 - h1, v0 - h0);
}
__device__ __forceinline__ void mma_bf16(float* c, const unsigned* a, unsigned b0, unsigned b1) {
    asm volatile(
        "mma.sync.aligned.m16n8k16.row.col.f32.bf16.bf16.f32 "
        "{%0,%1,%2,%3},{%4,%5,%6,%7},{%8,%9},{%0,%1,%2,%3};"
        : "+f"(c[0]), "+f"(c[1]), "+f"(c[2]), "+f"(c[3])
        : "r"(a[0]), "r"(a[1]), "r"(a[2]), "r"(a[3]), "r"(b0), "r"(b1));
}

// ---------------- scratch (device globals; no allocation) ----------------
__device__ float g_xs_part[TSPLIT*BB*KK*DD];
__device__ float g_xm_part[TSPLIT*BB*DD];
__device__ float g_xs[BB*KK*DD];                 // (b*32+k, j) fp32
__device__ unsigned g_xs_h[BB*KK*DD/2];          // pre-split bf16 hi pairs
__device__ unsigned g_xs_l[BB*KK*DD/2];          // pre-split bf16 lo pairs
__device__ float g_xm[BB*DD];
__device__ float g_qm[BB*DD];                    // qm[b, h*64+d]
__device__ float g_sp_part[KSPL_B*BB*KK*D3];     // spec3 partials (2 slabs)
__device__ float g_resp[BH*KK];
__device__ float g_M_part[KSPL_D*BB*KK*DD];
__device__ float g_M[BB*KK*DD];                  // (b, k, i)

// =============== 1) xs[b,k,j] = sum_t basis[b,t,k]*x[b,t,j] (+xm) ============
// bf16 3-term tensor version. grid (b=4, jt=4, ts=16), 256 threads.
__global__ void __launch_bounds__(256)
xs_kernel(const float* __restrict__ x, const float* __restrict__ basis) {
    __shared__ float xt[32][260];
    __shared__ unsigned bph[32][20];
    __shared__ unsigned bpl[32][20];
    __shared__ float xmred[4][256];
    const int b  = blockIdx.x;
    const int jt = blockIdx.y;
    const int ts = blockIdx.z;
    const int tid  = threadIdx.x;
    const int w    = tid >> 5;
    const int lane = tid & 31;
    const int g    = lane >> 2;
    const int tg   = lane & 3;
    const int j0   = jt * 256;

    float c[2][4][4];
#pragma unroll
    for (int i = 0; i < 2; i++)
#pragma unroll
        for (int j = 0; j < 4; j++)
#pragma unroll
            for (int r = 0; r < 4; r++) c[i][j][r] = 0.f;
    float4 xmacc = make_float4(0.f, 0.f, 0.f, 0.f);

    float4 xv[8];
    float4 bv0, bv1;
    const int bt2 = tid >> 3;
    const int bk4 = (tid & 7) * 4;

    {
        const int t0 = ts*256;
#pragma unroll
        for (int i = 0; i < 8; i++) {
            int f = tid + 256*i;
            int row = f >> 6, c4 = (f & 63) * 4;
            xv[i] = *(const float4*)(x + ((size_t)(b*TT + t0 + row))*DD + j0 + c4);
        }
        if (tid < 128) {
            bv0 = *(const float4*)(basis + ((size_t)(b*TT + t0 + 2*bt2  ))*KK + bk4);
            bv1 = *(const float4*)(basis + ((size_t)(b*TT + t0 + 2*bt2+1))*KK + bk4);
        }
    }

    for (int tc = 0; tc < 8; tc++) {
#pragma unroll
        for (int i = 0; i < 8; i++) {
            int f = tid + 256*i;
            int row = f >> 6, c4 = (f & 63) * 4;
            *(float4*)&xt[row][c4] = xv[i];
            xmacc.x += xv[i].x; xmacc.y += xv[i].y; xmacc.z += xv[i].z; xmacc.w += xv[i].w;
        }
        if (tid < 128) {
            float e0[4] = {bv0.x, bv0.y, bv0.z, bv0.w};
            float e1[4] = {bv1.x, bv1.y, bv1.z, bv1.w};
#pragma unroll
            for (int kk = 0; kk < 4; kk++) {
                unsigned h, l;
                split2(e0[kk], e1[kk], h, l);
                bph[bk4 + kk][bt2] = h;
                bpl[bk4 + kk][bt2] = l;
            }
        }
        __syncthreads();

        if (tc < 7) {
            const int t0 = ts*256 + (tc+1)*32;
#pragma unroll
            for (int i = 0; i < 8; i++) {
                int f = tid + 256*i;
                int row = f >> 6, c4 = (f & 63) * 4;
                xv[i] = *(const float4*)(x + ((size_t)(b*TT + t0 + row))*DD + j0 + c4);
            }
            if (tid < 128) {
                bv0 = *(const float4*)(basis + ((size_t)(b*TT + t0 + 2*bt2  ))*KK + bk4);
                bv1 = *(const float4*)(basis + ((size_t)(b*TT + t0 + 2*bt2+1))*KK + bk4);
            }
        }

#pragma unroll
        for (int s = 0; s < 2; s++) {
            unsigned ah[2][4], al[2][4];
#pragma unroll
            for (int mt = 0; mt < 2; mt++) {
                int mb = mt*16;
                ah[mt][0] = bph[mb+g  ][s*8+tg];   ah[mt][1] = bph[mb+g+8][s*8+tg];
                ah[mt][2] = bph[mb+g  ][s*8+tg+4]; ah[mt][3] = bph[mb+g+8][s*8+tg+4];
                al[mt][0] = bpl[mb+g  ][s*8+tg];   al[mt][1] = bpl[mb+g+8][s*8+tg];
                al[mt][2] = bpl[mb+g  ][s*8+tg+4]; al[mt][3] = bpl[mb+g+8][s*8+tg+4];
            }
#pragma unroll
            for (int nt = 0; nt < 4; nt++) {
                int jl = w*32 + nt*8 + g;
                int tb = s*16 + 2*tg;
                float x0 = xt[tb  ][jl], x1 = xt[tb+1][jl];
                float x2 = xt[tb+8][jl], x3 = xt[tb+9][jl];
                unsigned b0h, b0l, b1h, b1l;
                split2(x0, x1, b0h, b0l);
                split2(x2, x3, b1h, b1l);
#pragma unroll
                for (int mt = 0; mt < 2; mt++) {
                    mma_bf16(c[mt][nt], ah[mt], b0h, b1h);
                    mma_bf16(c[mt][nt], ah[mt], b0l, b1l);
                    mma_bf16(c[mt][nt], al[mt], b0h, b1h);
                }
            }
        }
        __syncthreads();
    }

#pragma unroll
    for (int mt = 0; mt < 2; mt++)
#pragma unroll
        for (int nt = 0; nt < 4; nt++) {
            int krow = mt*16 + g;
            int jc = j0 + w*32 + nt*8 + 2*tg;
            size_t base = (((size_t)ts*BB + b)*KK + krow)*DD + jc;
            *(float2*)&g_xs_part[base]        = make_float2(c[mt][nt][0], c[mt][nt][1]);
            *(float2*)&g_xs_part[base + 8*DD] = make_float2(c[mt][nt][2], c[mt][nt][3]);
        }
    *(float4*)&xmred[tid >> 6][(tid & 63) * 4] = xmacc;
    __syncthreads();
    if (tid < 64) {
        float4 s = make_float4(0.f, 0.f, 0.f, 0.f);
#pragma unroll
        for (int r = 0; r < 4; r++) {
            float4 v = *(const float4*)&xmred[r][tid*4];
            s.x += v.x; s.y += v.y; s.z += v.z; s.w += v.w;
        }
        *(float4*)&g_xm_part[((size_t)ts*BB + b)*DD + j0 + tid*4] = s;
    }
}

// =============== 2) reduce xs partials + xm, emit pre-split bf16 pairs ======
__global__ void reduceA_kernel() {
    int gid = blockIdx.x * 256 + threadIdx.x;   // 65536 float2 items
    float2 s = make_float2(0.f, 0.f);
#pragma unroll
    for (int ts = 0; ts < TSPLIT; ts++) {
        float2 v = ((const float2*)g_xs_part)[(size_t)ts*65536 + gid];
        s.x += v.x; s.y += v.y;
    }
    ((float2*)g_xs)[gid] = s;
    unsigned h, l;
    split2(s.x, s.y, h, l);
    g_xs_h[gid] = h;
    g_xs_l[gid] = l;
    if (gid < BB*DD) {
        float m = 0.f;
#pragma unroll
        for (int ts = 0; ts < TSPLIT; ts++) m += g_xm_part[(size_t)ts*BB*DD + gid];
        g_xm[gid] = m * (1.0f / (float)TT);
    }
}

// =============== 3) spec3 partials = xs(128x1024) @ Wqkv^T, bf16 3-term ======
// grid (nt=192, ks=2), 256 threads; block M=128, N=16, K=512 in chunks of 64.
// Warp w owns m rows [w*16, w*16+16). A comes pre-split (pure copy staging).
__global__ void __launch_bounds__(256)
gemmB_kernel(const float* __restrict__ Wqkv) {
    __shared__ unsigned Aph[128][36];    // [m][kpair 0..31], pad 36
    __shared__ unsigned Apl[128][36];
    __shared__ unsigned Bph[16][36];
    __shared__ unsigned Bpl[16][36];
    const int bn = blockIdx.x * 16;
    const int ks = blockIdx.y;
    const int tid  = threadIdx.x;
    const int w    = tid >> 5;
    const int lane = tid & 31;
    const int g    = lane >> 2;
    const int tg   = lane & 3;
    const int mb   = w * 16;             // warp m base

    float c[2][4];                       // [ntile][reg]
#pragma unroll
    for (int j = 0; j < 2; j++)
#pragma unroll
        for (int r = 0; r < 4; r++) c[j][r] = 0.f;

    for (int kc = 0; kc < 8; kc++) {
        const int k0 = ks*512 + kc*64;
        const int pb = k0 >> 1;          // pair base (32 pairs per chunk)
        // stage A from pre-split arrays: 128 rows x 32 pairs (1024 uint4 slots)
#pragma unroll
        for (int i = 0; i < 4; i++) {
            int f = tid + 256*i;
            int m = f >> 3, pg = (f & 7) * 4;
            uint4 vh = *(const uint4*)&g_xs_h[(size_t)m*512 + pb + pg];
            uint4 vl = *(const uint4*)&g_xs_l[(size_t)m*512 + pb + pg];
            Aph[m][pg+0] = vh.x; Aph[m][pg+1] = vh.y; Aph[m][pg+2] = vh.z; Aph[m][pg+3] = vh.w;
            Apl[m][pg+0] = vl.x; Apl[m][pg+1] = vl.y; Apl[m][pg+2] = vl.z; Apl[m][pg+3] = vl.w;
        }
        // stage B (Wqkv 16n x 64k): 256 float4 slots, split on the fly
        {
            int n = tid >> 4, kg = tid & 15;
            float4 v = *(const float4*)(Wqkv + (size_t)(bn + n)*DD + k0 + kg*4);
            unsigned h0, l0, h1, l1;
            split2(v.x, v.y, h0, l0);
            split2(v.z, v.w, h1, l1);
            Bph[n][kg*2] = h0; Bph[n][kg*2+1] = h1;
            Bpl[n][kg*2] = l0; Bpl[n][kg*2+1] = l1;
        }
        __syncthreads();
#pragma unroll
        for (int s = 0; s < 4; s++) {
            unsigned ah[4], al[4];
            ah[0] = Aph[mb+g  ][s*8+tg];   ah[1] = Aph[mb+g+8][s*8+tg];
            ah[2] = Aph[mb+g  ][s*8+tg+4]; ah[3] = Aph[mb+g+8][s*8+tg+4];
            al[0] = Apl[mb+g  ][s*8+tg];   al[1] = Apl[mb+g+8][s*8+tg];
            al[2] = Apl[mb+g  ][s*8+tg+4]; al[3] = Apl[mb+g+8][s*8+tg+4];
#pragma unroll
            for (int nt = 0; nt < 2; nt++) {
                int nr = nt*8 + g;
                unsigned b0h = Bph[nr][s*8+tg], b1h = Bph[nr][s*8+tg+4];
                unsigned b0l = Bpl[nr][s*8+tg], b1l = Bpl[nr][s*8+tg+4];
                mma_bf16(c[nt], ah, b0h, b1h);
                mma_bf16(c[nt], ah, b0l, b1l);
                mma_bf16(c[nt], al, b0h, b1h);
            }
        }
        __syncthreads();
    }
#pragma unroll
    for (int nt = 0; nt < 2; nt++) {
        int m = mb + g;
        int n = bn + nt*8 + 2*tg;
        size_t base = ((size_t)ks*128 + m)*D3 + n;
        *(float2*)&g_sp_part[base]                = make_float2(c[nt][0], c[nt][1]);
        *(float2*)&g_sp_part[base + 8*(size_t)D3] = make_float2(c[nt][2], c[nt][3]);
    }
}

// =============== 4a) qm GEMV: qm[b,row] = dot(Wq[row], xm[b]) ===============
__global__ void __launch_bounds__(256)
qm_kernel(const float* __restrict__ Wqkv) {
    __shared__ float sxm[BB*DD];
    const int tid  = threadIdx.x;
    const int w    = tid >> 5;
    const int lane = tid & 31;
#pragma unroll
    for (int i = 0; i < 4; i++)
        ((float4*)sxm)[tid + 256*i] = ((const float4*)g_xm)[tid + 256*i];
    __syncthreads();

    const int row = blockIdx.x * 8 + w;
    const float4* wr = (const float4*)(Wqkv + (size_t)row*DD);
    float s0 = 0.f, s1 = 0.f, s2 = 0.f, s3 = 0.f;
#pragma unroll
    for (int i = 0; i < 8; i++) {
        float4 wv = wr[lane + 32*i];
        float4 x0 = *(const float4*)&sxm[0*DD + (lane + 32*i)*4];
        float4 x1 = *(const float4*)&sxm[1*DD + (lane + 32*i)*4];
        float4 x2 = *(const float4*)&sxm[2*DD + (lane + 32*i)*4];
        float4 x3 = *(const float4*)&sxm[3*DD + (lane + 32*i)*4];
        s0 += wv.x*x0.x + wv.y*x0.y + wv.z*x0.z + wv.w*x0.w;
        s1 += wv.x*x1.x + wv.y*x1.y + wv.z*x1.z + wv.w*x1.w;
        s2 += wv.x*x2.x + wv.y*x2.y + wv.z*x2.z + wv.w*x2.w;
        s3 += wv.x*x3.x + wv.y*x3.y + wv.z*x3.z + wv.w*x3.w;
    }
#pragma unroll
    for (int off = 16; off > 0; off >>= 1) {
        s0 += __shfl_down_sync(0xffffffffu, s0, off);
        s1 += __shfl_down_sync(0xffffffffu, s1, off);
        s2 += __shfl_down_sync(0xffffffffu, s2, off);
        s3 += __shfl_down_sync(0xffffffffu, s3, off);
    }
    if (lane == 0) {
        g_qm[0*DD + row] = s0;
        g_qm[1*DD + row] = s1;
        g_qm[2*DD + row] = s2;
        g_qm[3*DD + row] = s3;
    }
}

// =============== 4b) fused soliton ODE + pulse MLP ===============
__global__ void ps_kernel(const float* __restrict__ W1, const float* __restrict__ b1,
                          const float* __restrict__ W2, const float* __restrict__ b2,
                          const float* __restrict__ sfilt,
                          const float* __restrict__ pa, const float* __restrict__ pb,
                          float* __restrict__ out_pw, float* __restrict__ out_resp) {
    if (blockIdx.x < 64) {
        // ---- soliton ----
        const int bh = blockIdx.x;
        const int b = bh >> 4, h = bh & 15;
        const int k = threadIdx.x;
        if (k >= 32) return;
        const size_t m = (size_t)(b*KK + k);
        const float* P0 = g_sp_part + m*D3;
        const float* P1 = g_sp_part + (128 + m)*D3;
        float dot = 0.f;
#pragma unroll
        for (int d = 0; d < HDIM/4; d++) {
            float4 q0 = *(const float4*)(P0 + h*HDIM + d*4);
            float4 q1 = *(const float4*)(P1 + h*HDIM + d*4);
            float4 k0 = *(const float4*)(P0 + DD + h*HDIM + d*4);
            float4 k1 = *(const float4*)(P1 + DD + h*HDIM + d*4);
            dot += (q0.x+q1.x)*(k0.x+k1.x) + (q0.y+q1.y)*(k0.y+k1.y)
                 + (q0.z+q1.z)*(k0.z+k1.z) + (q0.w+q1.w)*(k0.w+k1.w);
        }
        float filt = 1.f / (1.f + expf(-sfilt[h*KK + k]));
        float s = dot * 0.125f * filt;

        float scale = fmaxf(fabsf(s), 1e-6f);
        float sn = s / scale;
        float I  = (fabsf(s) > 0.5f) ? sn : 0.1f*sn;
        const float a = *pa, bcoef = *pb;
        const float dt = 0.2f;
        float v = 0.f, w = 0.f;
#pragma unroll
        for (int it = 0; it < 5; it++) {
            float dv = v - v*v*v*(1.f/3.f) - w + I;
            float dw = (v + a - bcoef*w) * 10.f;
            v = fminf(fmaxf(v + dt*dv, -3.f), 3.f);
            w = fminf(fmaxf(w + dt*dw, -3.f), 3.f);
        }
        float r = v * scale;
        g_resp[bh*KK + k]   = r;
        out_resp[bh*KK + k] = r;
    } else {
        // ---- pulse MLP ----
        __shared__ float qm[HDIM];
        __shared__ float h1[32];
        const int bh = blockIdx.x - 64;
        const int b = bh >> 4, h = bh & 15;
        const int d = threadIdx.x;
        qm[d] = g_qm[(size_t)b*DD + h*HDIM + d];
        __syncthreads();
        if (d < 32) {
            float a = b1[d];
#pragma unroll
            for (int j = 0; j < HDIM; j++) a += qm[j] * W1[d*HDIM + j];
            h1[d] = a / (1.f + expf(-a));
        }
        __syncthreads();
        if (d == 0) {
            float a = b2[0];
#pragma unroll
            for (int j = 0; j < 32; j++) a += h1[j] * W2[j];
            float spl = (a > 20.f) ? a : log1pf(expf(a));
            out_pw[bh] = 4.0f + spl;
        }
    }
}

// =============== 5) M[b] = (resp*v_spec)(32x1024) @ Wout^T, split-K ==========
__global__ void __launch_bounds__(256)
gemmD_kernel(const float* __restrict__ Wout) {
    __shared__ float As[8][32];
    __shared__ float Bs[8][128];
    const int bn = blockIdx.x * 128;
    const int ks = blockIdx.y;
    const int b  = blockIdx.z;
    const int tid = threadIdx.x;
    const int tx = tid & 31;
    const int my = tid >> 5;
    const int lr = tid >> 1, lc = (tid & 1) << 2;

    const float* Bp = Wout + (size_t)(bn + lr)*DD + ks*128 + lc;

    ull acc2[4][2];
#pragma unroll
    for (int i = 0; i < 4; i++) { acc2[i][0] = 0ull; acc2[i][1] = 0ull; }

    for (int k0 = 0; k0 < 128; k0 += 8) {
        if (tid < 64) {
            int ar = tid >> 1, ac = (tid & 1) << 2;
            int col = ks*128 + k0 + ac;
            size_t m = (size_t)(b*KK + ar);
            float4 a0 = *(const float4*)(g_sp_part + m*D3 + 2*DD + col);
            float4 a1 = *(const float4*)(g_sp_part + (128 + m)*D3 + 2*DD + col);
            float r = g_resp[(b*HH + (col >> 6))*KK + ar];
            As[ac+0][ar] = (a0.x + a1.x) * r; As[ac+1][ar] = (a0.y + a1.y) * r;
            As[ac+2][ar] = (a0.z + a1.z) * r; As[ac+3][ar] = (a0.w + a1.w) * r;
        }
        float4 bv = *(const float4*)(Bp + k0);
        Bs[lc+0][lr] = bv.x; Bs[lc+1][lr] = bv.y; Bs[lc+2][lr] = bv.z; Bs[lc+3][lr] = bv.w;
        __syncthreads();
#pragma unroll
        for (int kk = 0; kk < 8; kk++) {
            ulonglong2 rb = *(const ulonglong2*)&Bs[kk][tx*4];
            float a0 = As[kk][my], a1 = As[kk][my+8], a2 = As[kk][my+16], a3 = As[kk][my+24];
            ull p0 = pk2(a0,a0), p1 = pk2(a1,a1), p2 = pk2(a2,a2), p3 = pk2(a3,a3);
            ffma2(acc2[0][0], p0, rb.x); ffma2(acc2[0][1], p0, rb.y);
            ffma2(acc2[1][0], p1, rb.x); ffma2(acc2[1][1], p1, rb.y);
            ffma2(acc2[2][0], p2, rb.x); ffma2(acc2[2][1], p2, rb.y);
            ffma2(acc2[3][0], p3, rb.x); ffma2(acc2[3][1], p3, rb.y);
        }
        __syncthreads();
    }
#pragma unroll
    for (int mi = 0; mi < 4; mi++) {
        int m = my + 8*mi;
        *(ulonglong2*)&g_M_part[(((size_t)ks*BB + b)*KK + m)*DD + bn + tx*4] =
            make_ulonglong2(acc2[mi][0], acc2[mi][1]);
    }
}

__global__ void reduceD_kernel() {
    int gid = blockIdx.x * 256 + threadIdx.x;   // 131072
    float s = 0.f;
#pragma unroll
    for (int ks = 0; ks < KSPL_D; ks++) s += g_M_part[(size_t)ks*131072 + gid];
    g_M[gid] = s;
}

// =============== 6) out[b,t,j] = sum_k basis[b,t,k] * M[b,k,j], tf32 tensor ==
__global__ void __launch_bounds__(256)
out_kernel(const float* __restrict__ basis, float* __restrict__ out) {
    __shared__ float Bh[64][36];
    __shared__ float Bl[64][36];
    __shared__ float Mh[32][72];
    __shared__ float Ml[32][72];
    const int tt = blockIdx.x, jt = blockIdx.y, b = blockIdx.z;
    const int t0 = tt*64, j0 = jt*64;
    const int tid  = threadIdx.x;
    const int w    = tid >> 5;
    const int lane = tid & 31;
    const int g    = lane >> 2;
    const int tg   = lane & 3;
    const int wm   = w >> 2;
    const int wn   = w & 3;

#pragma unroll
    for (int i = 0; i < 2; i++) {
        int f = tid + 256*i;
        int row = f >> 3, c4 = (f & 7) * 4;
        float4 v = *(const float4*)(basis + ((size_t)(b*TT + t0 + row))*KK + c4);
        float hx = tf32_rna(v.x), hy = tf32_rna(v.y), hz = tf32_rna(v.z), hw = tf32_rna(v.w);
        Bh[row][c4+0] = hx; Bh[row][c4+1] = hy; Bh[row][c4+2] = hz; Bh[row][c4+3] = hw;
        Bl[row][c4+0] = v.x - hx; Bl[row][c4+1] = v.y - hy;
        Bl[row][c4+2] = v.z - hz; Bl[row][c4+3] = v.w - hw;
    }
#pragma unroll
    for (int i = 0; i < 2; i++) {
        int f = tid + 256*i;
        int row = f >> 4, c4 = (f & 15) * 4;
        float4 v = *(const float4*)(g_M + ((size_t)b*KK + row)*DD + j0 + c4);
        float hx = tf32_rna(v.x), hy = tf32_rna(v.y), hz = tf32_rna(v.z), hw = tf32_rna(v.w);
        Mh[row][c4+0] = hx; Mh[row][c4+1] = hy; Mh[row][c4+2] = hz; Mh[row][c4+3] = hw;
        Ml[row][c4+0] = v.x - hx; Ml[row][c4+1] = v.y - hy;
        Ml[row][c4+2] = v.z - hz; Ml[row][c4+3] = v.w - hw;
    }
    __syncthreads();

    float c[2][2][4];
#pragma unroll
    for (int i = 0; i < 2; i++)
#pragma unroll
        for (int j = 0; j < 2; j++)
#pragma unroll
            for (int r = 0; r < 4; r++) c[i][j][r] = 0.f;

#pragma unroll
    for (int s = 0; s < 4; s++) {
        const int k0 = s*8 + tg, k1 = s*8 + tg + 4;
        float ah[2][4], al[2][4];
#pragma unroll
        for (int mt = 0; mt < 2; mt++) {
            int mb = wm*32 + mt*16;
            ah[mt][0] = Bh[mb+g][k0];  ah[mt][1] = Bh[mb+g+8][k0];
            ah[mt][2] = Bh[mb+g][k1];  ah[mt][3] = Bh[mb+g+8][k1];
            al[mt][0] = Bl[mb+g][k0];  al[mt][1] = Bl[mb+g+8][k0];
            al[mt][2] = Bl[mb+g][k1];  al[mt][3] = Bl[mb+g+8][k1];
        }
#pragma unroll
        for (int nt = 0; nt < 2; nt++) {
            int nc = wn*16 + nt*8 + g;
            float b0h = Mh[k0][nc], b1h = Mh[k1][nc];
            float b0l = Ml[k0][nc], b1l = Ml[k1][nc];
#pragma unroll
            for (int mt = 0; mt < 2; mt++) {
                mma_tf32(c[mt][nt], ah[mt], b0h, b1h);
                mma_tf32(c[mt][nt], ah[mt], b0l, b1l);
                mma_tf32(c[mt][nt], al[mt], b0h, b1h);
            }
        }
    }
#pragma unroll
    for (int mt = 0; mt < 2; mt++)
#pragma unroll
        for (int nt = 0; nt < 2; nt++) {
            int t = t0 + wm*32 + mt*16 + g;
            int jc = j0 + wn*16 + nt*8 + 2*tg;
            size_t base = ((size_t)b*TT + t)*DD + jc;
            *(float2*)(out + base)                = make_float2(c[mt][nt][0], c[mt][nt][1]);
            *(float2*)(out + base + 8*(size_t)DD) = make_float2(c[mt][nt][2], c[mt][nt][3]);
        }
}

// ---------------- launch ----------------
extern "C" void kernel_launch(void* const* d_in, const int* in_sizes, int n_in,
                              void* d_out, int out_size) {
    const float* x     = (const float*)d_in[0];
    const float* basis = (const float*)d_in[1];
    const float* Wqkv  = (const float*)d_in[2];
    const float* Wout  = (const float*)d_in[3];
    const float* pa    = (const float*)d_in[4];
    const float* pb    = (const float*)d_in[5];
    const float* W1    = (const float*)d_in[6];
    const float* b1    = (const float*)d_in[7];
    const float* W2    = (const float*)d_in[8];
    const float* b2    = (const float*)d_in[9];
    const float* sfilt = (const float*)d_in[10];

    float* out      = (float*)d_out;                 // (B,T,D)
    float* out_pw   = out + (size_t)BB*TT*DD;        // (B,H)
    float* out_resp = out_pw + BH;                   // (B,H,K)

    xs_kernel<<<dim3(BB, 4, TSPLIT), 256>>>(x, basis);
    reduceA_kernel<<<256, 256>>>();
    qm_kernel<<<128, 256>>>(Wqkv);
    gemmB_kernel<<<dim3(192, KSPL_B), 256>>>(Wqkv);
    ps_kernel<<<128, 64>>>(W1, b1, W2, b2, sfilt, pa, pb, out_pw, out_resp);
    gemmD_kernel<<<dim3(8, KSPL_D, BB), 256>>>(Wout);
    reduceD_kernel<<<512, 256>>>();
    out_kernel<<<dim3(64, 16, BB), 256>>>(basis, out);
}